// round 1
// baseline (speedup 1.0000x reference)
#include <cuda_runtime.h>
#include <math.h>
#include <stdint.h>

#define NN     4096
#define BB     2
#define FIN    128
#define FOUT   64
#define NW     (NN/32)          // 128 bitmask words per row
#define ALPHA  0.2f
#define NEG_INF (-9.0e15f)

// ---------------- scratch (device globals; no allocation allowed) ----------
__device__ float    g_Wh[BB*NN*FOUT];     // 2 MB
__device__ float    g_s1[BB*NN];
__device__ float    g_s2[BB*NN];
__device__ float    g_m [BB*NN];
__device__ float    g_Z [BB*NN];
__device__ unsigned g_adjbits[NN*NW];     // 2 MB bitmask

using u64 = unsigned long long;

__device__ __forceinline__ u64 ffma2(u64 a, u64 b, u64 c) {
    u64 d;
    asm("fma.rn.f32x2 %0, %1, %2, %3;" : "=l"(d) : "l"(a), "l"(b), "l"(c));
    return d;
}
__device__ __forceinline__ float2 unpack2(u64 v) {
    float2 r;
    r.x = __uint_as_float((unsigned)(v & 0xffffffffull));
    r.y = __uint_as_float((unsigned)(v >> 32));
    return r;
}
__device__ __forceinline__ float elu1(float v) {
    return v > 0.f ? v : expm1f(v);
}

// ---------------- K1: Wh = h@W, s1 = Wh@a1, s2 = Wh@a2 --------------------
__global__ __launch_bounds__(256) void k_proj(const float* __restrict__ h,
                                              const float* __restrict__ W,
                                              const float* __restrict__ a) {
    __shared__ float  Ws[FIN*FOUT];   // 32 KB
    __shared__ float  hS[4*FIN];      // 4 rows
    __shared__ float2 sred[8];
    int tid = threadIdx.x;
    for (int k = tid; k < FIN*FOUT; k += 256) Ws[k] = W[k];
    int rowbase = blockIdx.x * 4;
    const float* hsrc = h + (size_t)rowbase * FIN;
    for (int k = tid; k < 4*FIN; k += 256) hS[k] = hsrc[k];
    __syncthreads();

    int o = tid & 63, r = tid >> 6;
    float acc = 0.f;
    const float4* h4 = (const float4*)(hS + r * FIN);
#pragma unroll
    for (int f4 = 0; f4 < FIN/4; f4++) {
        float4 hv = h4[f4];
        acc = fmaf(hv.x, Ws[(f4*4+0)*FOUT + o], acc);
        acc = fmaf(hv.y, Ws[(f4*4+1)*FOUT + o], acc);
        acc = fmaf(hv.z, Ws[(f4*4+2)*FOUT + o], acc);
        acc = fmaf(hv.w, Ws[(f4*4+3)*FOUT + o], acc);
    }
    int rr = rowbase + r;
    g_Wh[(size_t)rr * FOUT + o] = acc;

    float p1 = acc * __ldg(a + o);
    float p2 = acc * __ldg(a + FOUT + o);
#pragma unroll
    for (int off = 16; off; off >>= 1) {
        p1 += __shfl_xor_sync(0xffffffffu, p1, off);
        p2 += __shfl_xor_sync(0xffffffffu, p2, off);
    }
    int wid = tid >> 5;
    if ((tid & 31) == 0) sred[wid] = make_float2(p1, p2);
    __syncthreads();
    if (tid < 4) {
        float2 x = sred[tid*2], y = sred[tid*2+1];
        g_s1[rowbase + tid] = x.x + y.x;
        g_s2[rowbase + tid] = x.y + y.y;
    }
}

// ---------------- K2: pack adj (int32 0/1) -> bitmask ---------------------
__global__ __launch_bounds__(256) void k_pack(const int* __restrict__ adj) {
    int lane = threadIdx.x & 31;
    int gw = (blockIdx.x * blockDim.x + threadIdx.x) >> 5;
    int nw = (gridDim.x * blockDim.x) >> 5;
    const int W32 = NN * NW;
    for (int w = gw; w < W32; w += nw) {
        int v = adj[(size_t)w * 32 + lane];
        unsigned bal = __ballot_sync(0xffffffffu, v > 0);
        if (lane == 0) g_adjbits[w] = bal;
    }
}

// ---------------- K3: per-row softmax stats m, Z --------------------------
__global__ __launch_bounds__(256) void k_stats() {
    int lane = threadIdx.x & 31;
    int row  = blockIdx.x * 8 + (threadIdx.x >> 5);   // 0..8191
    int b = row >> 12, i = row & (NN - 1);
    float s1i = g_s1[row];
    const unsigned* wrow = g_adjbits + (size_t)i * NW;
    const float* s2p = g_s2 + ((size_t)b << 12);

    float m = NEG_INF;
    for (int it = 0; it < NW; it++) {
        unsigned word = wrow[it];
        float e = s1i + s2p[it*32 + lane];
        e = e >= 0.f ? e : ALPHA * e;
        float sel = ((word >> lane) & 1u) ? e : NEG_INF;
        m = fmaxf(m, sel);
    }
#pragma unroll
    for (int off = 16; off; off >>= 1) m = fmaxf(m, __shfl_xor_sync(0xffffffffu, m, off));

    float z = 0.f;
    for (int it = 0; it < NW; it++) {
        unsigned word = wrow[it];
        float e = s1i + s2p[it*32 + lane];
        e = e >= 0.f ? e : ALPHA * e;
        float sel = ((word >> lane) & 1u) ? e : NEG_INF;
        z += __expf(sel - m);   // masked: exp(-huge)=0; degenerate row: exp(0)=1
    }
#pragma unroll
    for (int off = 16; off; off >>= 1) z += __shfl_xor_sync(0xffffffffu, z, off);
    if (lane == 0) { g_m[row] = m; g_Z[row] = z; }
}

// ---------------- K4: fused softmax(P) @ Wh, ELU epilogue -----------------
// Grid (128, 2): 32 rows per CTA per batch. TJ=128 j-tile.
#define TJ 128
#define IB 32

__global__ __launch_bounds__(256, 2) void k_main(float* __restrict__ out) {
    extern __shared__ float sm[];
    float*  WhS  = sm;                               // TJ*64 = 8192 floats
    float2* pSd  = (float2*)(sm + TJ*FOUT);          // TJ*IB float2 = 8192 floats
    float*  s2S  = sm + TJ*FOUT + TJ*IB*2;           // 128
    float*  s1S  = s2S + TJ;                         // 32
    float*  mS   = s1S + IB;                         // 32
    unsigned* adjS = (unsigned*)(mS + IB);           // IB*5 words (padded)

    int tid = threadIdx.x;
    int b = blockIdx.y;
    int i0 = blockIdx.x * IB;

    if (tid < IB) {
        s1S[tid] = g_s1[b*NN + i0 + tid];
        mS[tid]  = g_m [b*NN + i0 + tid];
    }

    // phase-A mapping
    int ai = tid & 31, ajh = tid >> 5;               // row, j-sixteenth
    // phase-B mapping: 4 feat-groups x 8 row-groups per warp
    int lane = tid & 31, w = tid >> 5;
    int og = (w & 3) * 4 + (lane & 3);               // 0..15 -> feats og*4..+3
    int rg = (w >> 2) * 8 + (lane >> 2);             // 0..15 -> rows  rg*2..+1

    u64 acc0 = 0, acc1 = 0, acc2 = 0, acc3 = 0;

    for (int t = 0; t < NN/TJ; t++) {
        int j0 = t * TJ;
        __syncthreads();   // previous tile's consumers done (also covers s1S/mS init)

        // ---- phase 0: stage Wh tile, s2 tile, adj words ----
        {
            const float4* src = (const float4*)(g_Wh + ((size_t)(b*NN + j0)) * FOUT);
            float4* dst = (float4*)WhS;
#pragma unroll
            for (int k = 0; k < 8; k++) dst[tid + k*256] = src[tid + k*256];
            if (tid < 32)
                ((float4*)s2S)[tid] = ((const float4*)(g_s2 + b*NN + j0))[tid];
            if (tid < 128) {
                int ir = tid >> 2, wq = tid & 3;
                adjS[ir*5 + wq] = g_adjbits[(size_t)(i0 + ir) * NW + (j0 >> 5) + wq];
            }
        }
        __syncthreads();

        // ---- phase A: compute duplicated softmax numerators into pSd ----
        {
            float s1i = s1S[ai], mi = mS[ai];
            unsigned word = adjS[ai*5 + (ajh >> 1)];
            int bshift = (ajh & 1) * 16;
#pragma unroll
            for (int tt = 0; tt < 16; tt++) {
                int jj = ajh*16 + tt;
                float e = s1i + s2S[jj];
                e = e >= 0.f ? e : ALPHA * e;
                float sel = ((word >> (bshift + tt)) & 1u) ? e : NEG_INF;
                float p = __expf(sel - mi);
                pSd[jj*IB + ai] = make_float2(p, p);
            }
        }
        __syncthreads();

        // ---- phase B: P-tile @ Wh-tile with f32x2 FMA ----
        {
            const ulonglong2* wb = (const ulonglong2*)WhS;   // 16 ull2 per j-row
            const ulonglong2* pb = (const ulonglong2*)pSd;   // 16 ull2 per j-row
#pragma unroll 8
            for (int j = 0; j < TJ; j++) {
                ulonglong2 wh = wb[j*16 + og];   // (f0,f1),(f2,f3)
                ulonglong2 pv = pb[j*16 + rg];   // (p_r0,p_r0),(p_r1,p_r1)
                acc0 = ffma2(pv.x, wh.x, acc0);
                acc1 = ffma2(pv.x, wh.y, acc1);
                acc2 = ffma2(pv.y, wh.x, acc2);
                acc3 = ffma2(pv.y, wh.y, acc3);
            }
        }
    }

    // ---- epilogue: /Z, ELU, store ----
    int r0  = i0 + rg*2;
    int rr0 = b*NN + r0;
    float inv0 = 1.f / g_Z[rr0];
    float inv1 = 1.f / g_Z[rr0 + 1];
    float2 v00 = unpack2(acc0), v01 = unpack2(acc1);
    float2 v10 = unpack2(acc2), v11 = unpack2(acc3);
    float4 o0 = make_float4(elu1(v00.x*inv0), elu1(v00.y*inv0),
                            elu1(v01.x*inv0), elu1(v01.y*inv0));
    float4 o1 = make_float4(elu1(v10.x*inv1), elu1(v10.y*inv1),
                            elu1(v11.x*inv1), elu1(v11.y*inv1));
    ((float4*)out)[(size_t)rr0     * (FOUT/4) + og] = o0;
    ((float4*)out)[(size_t)(rr0+1) * (FOUT/4) + og] = o1;
}

// ---------------- launch --------------------------------------------------
extern "C" void kernel_launch(void* const* d_in, const int* in_sizes, int n_in,
                              void* d_out, int out_size) {
    const float* h   = (const float*)d_in[0];
    const int*   adj = (const int*)  d_in[1];
    const float* W   = (const float*)d_in[2];
    const float* a   = (const float*)d_in[3];
    float* out = (float*)d_out;

    const int smem_main = (TJ*FOUT + TJ*IB*2 + TJ + IB + IB) * 4 + IB*5*4;
    cudaFuncSetAttribute(k_main, cudaFuncAttributeMaxDynamicSharedMemorySize, smem_main);

    k_proj <<<(BB*NN)/4, 256>>>(h, W, a);
    k_pack <<<1024, 256>>>(adj);
    k_stats<<<(BB*NN)/8, 256>>>();
    k_main <<<dim3(NN/IB, BB), 256, smem_main>>>(out);
}

// round 4
// speedup vs baseline: 1.5232x; 1.5232x over previous
#include <cuda_runtime.h>
#include <math.h>
#include <stdint.h>

#define NN     4096
#define BB     2
#define FIN    128
#define FOUT   64
#define NW     128
#define ALPHA  0.2f

#define S_SPLIT 8
#define MC      256
#define JC      (NN/S_SPLIT)   // 512
#define TJ      32
#define NTILE   (JC/TJ)        // 16

__device__ float    g_Wh[BB*NN*FOUT];
__device__ float    g_s1[BB*NN];
__device__ float    g_s2[BB*NN];
__device__ float    g_Z [BB*NN];
__device__ unsigned g_adjbits[NN*NW];
__device__ float    g_acc[BB*NN*FOUT];

using u64 = unsigned long long;

__device__ __forceinline__ u64 ffma2(u64 a, u64 b, u64 c) {
    u64 d;
    asm("fma.rn.f32x2 %0, %1, %2, %3;" : "=l"(d) : "l"(a), "l"(b), "l"(c));
    return d;
}
__device__ __forceinline__ u64 dup2(float x) {
    u64 d;
    asm("mov.b64 %0, {%1, %1};" : "=l"(d) : "f"(x));
    return d;
}
__device__ __forceinline__ float lo32(u64 v) { return __uint_as_float((unsigned)(v & 0xffffffffull)); }
__device__ __forceinline__ float hi32(u64 v) { return __uint_as_float((unsigned)(v >> 32)); }
__device__ __forceinline__ float elu1(float v) { return v > 0.f ? v : expm1f(v); }

// ---------------- K1: Wh = h@W, s1 = Wh@a1, s2 = Wh@a2 --------------------
__global__ __launch_bounds__(256) void k_proj(const float* __restrict__ h,
                                              const float* __restrict__ W,
                                              const float* __restrict__ a) {
    __shared__ float  Ws[FIN*FOUT];
    __shared__ float  hS[4*FIN];
    __shared__ float2 sred[8];
    int tid = threadIdx.x;
    for (int k = tid; k < FIN*FOUT; k += 256) Ws[k] = W[k];
    int rowbase = blockIdx.x * 4;
    const float* hsrc = h + (size_t)rowbase * FIN;
    for (int k = tid; k < 4*FIN; k += 256) hS[k] = hsrc[k];
    __syncthreads();

    int o = tid & 63, r = tid >> 6;
    float acc = 0.f;
    const float4* h4 = (const float4*)(hS + r * FIN);
#pragma unroll
    for (int f4 = 0; f4 < FIN/4; f4++) {
        float4 hv = h4[f4];
        acc = fmaf(hv.x, Ws[(f4*4+0)*FOUT + o], acc);
        acc = fmaf(hv.y, Ws[(f4*4+1)*FOUT + o], acc);
        acc = fmaf(hv.z, Ws[(f4*4+2)*FOUT + o], acc);
        acc = fmaf(hv.w, Ws[(f4*4+3)*FOUT + o], acc);
    }
    int rr = rowbase + r;
    g_Wh[(size_t)rr * FOUT + o] = acc;

    float p1 = acc * __ldg(a + o);
    float p2 = acc * __ldg(a + FOUT + o);
#pragma unroll
    for (int off = 16; off; off >>= 1) {
        p1 += __shfl_xor_sync(0xffffffffu, p1, off);
        p2 += __shfl_xor_sync(0xffffffffu, p2, off);
    }
    int wid = tid >> 5;
    if ((tid & 31) == 0) sred[wid] = make_float2(p1, p2);
    __syncthreads();
    if (tid < 4) {
        float2 x = sred[tid*2], y = sred[tid*2+1];
        g_s1[rowbase + tid] = x.x + y.x;
        g_s2[rowbase + tid] = x.y + y.y;
    }
}

// ---------------- K2: fused adj->bitmask pack + per-row Z (no max pass) ---
__global__ __launch_bounds__(256) void k_prep(const int* __restrict__ adj) {
    __shared__ float s2S[2*NN];        // 32 KB (both batches)
    __shared__ float red0[8], red1[8];
    int tid = threadIdx.x;
    for (int k = tid; k < (2*NN)/4; k += 256)
        ((float4*)s2S)[k] = ((const float4*)g_s2)[k];
    __syncthreads();

    int i0 = blockIdx.x * 4;
    for (int r = 0; r < 4; r++) {
        int i = i0 + r;
        float s10 = g_s1[i];
        float s11 = g_s1[NN + i];
        const int4* arow = (const int4*)(adj + (size_t)i * NN) + tid * 4;
        unsigned m16 = 0;
        float z0 = 0.f, z1 = 0.f;
#pragma unroll
        for (int q = 0; q < 4; q++) {
            int4 v = arow[q];
            int jb = tid * 16 + q * 4;
            int b4[4] = { v.x > 0, v.y > 0, v.z > 0, v.w > 0 };
#pragma unroll
            for (int c = 0; c < 4; c++) {
                if (b4[c]) m16 |= 1u << (q*4 + c);
                float e0 = s10 + s2S[jb + c];
                float e1 = s11 + s2S[NN + jb + c];
                float l0 = fmaxf(e0, ALPHA * e0);
                float l1 = fmaxf(e1, ALPHA * e1);
                z0 += b4[c] ? __expf(l0) : 0.f;
                z1 += b4[c] ? __expf(l1) : 0.f;
            }
        }
#pragma unroll
        for (int off = 16; off; off >>= 1) {
            z0 += __shfl_xor_sync(0xffffffffu, z0, off);
            z1 += __shfl_xor_sync(0xffffffffu, z1, off);
        }
        if ((tid & 31) == 0) { red0[tid>>5] = z0; red1[tid>>5] = z1; }
        unsigned other = __shfl_down_sync(0xffffffffu, m16, 1);
        if (!(tid & 1)) g_adjbits[(size_t)i * NW + (tid >> 1)] = m16 | (other << 16);
        __syncthreads();
        if (tid == 0)       { float s = 0; for (int k2 = 0; k2 < 8; k2++) s += red0[k2]; g_Z[i] = s; }
        else if (tid == 32) { float s = 0; for (int k2 = 0; k2 < 8; k2++) s += red1[k2]; g_Z[NN + i] = s; }
        __syncthreads();
    }
}

// ---------------- K3: zero accumulator ------------------------------------
__global__ void k_zero() {
    ((float4*)g_acc)[blockIdx.x * 256 + threadIdx.x] = make_float4(0.f, 0.f, 0.f, 0.f);
}

// ---------------- K4: K-split fused softmax-numerator GEMM ----------------
// Grid (16 rowtiles, 8 ksplits, 2 batches). CTA: 256 rows x 512 j.
// Per-thread: mi=8 rows x ni=8 feats; intensity 2B per f32x2 op.
#define SMEM_MAIN ((TJ*MC + TJ*FOUT + JC)*4 + MC*17*4)

__global__ __launch_bounds__(256, 2) void k_main() {
    extern __shared__ float sm[];
    float*    pS    = sm;                          // TJ*MC   = 8192 f (32KB)
    float*    whS   = sm + TJ*MC;                  // TJ*FOUT = 2048 f (8KB)
    float*    s2S   = sm + TJ*MC + TJ*FOUT;        // JC      = 512 f
    unsigned* bitsS = (unsigned*)(sm + TJ*MC + TJ*FOUT + JC);  // MC*17 (padded)

    int tid = threadIdx.x;
    int b   = blockIdx.z;
    int i0  = blockIdx.x * MC;
    int j0  = blockIdx.y * JC;

    // stage s2 chunk
    if (tid < JC/4)
        ((float4*)s2S)[tid] = *((const float4*)(g_s2 + b*NN + j0) + tid);
    // stage this CTA's bit words: row (i0+tid), 16 words
    {
        const uint4* src = (const uint4*)(g_adjbits + (size_t)(i0 + tid) * NW + (j0 >> 5));
        uint4 w0 = src[0], w1 = src[1], w2 = src[2], w3 = src[3];
        unsigned* dst = bitsS + tid * 17;
        dst[0]=w0.x; dst[1]=w0.y; dst[2]=w0.z;  dst[3]=w0.w;
        dst[4]=w1.x; dst[5]=w1.y; dst[6]=w1.z;  dst[7]=w1.w;
        dst[8]=w2.x; dst[9]=w2.y; dst[10]=w2.z; dst[11]=w2.w;
        dst[12]=w3.x; dst[13]=w3.y; dst[14]=w3.z; dst[15]=w3.w;
    }
    float s1r = g_s1[b*NN + i0 + tid];

    int fg = tid & 7;          // feats  [fg*8, fg*8+8)
    int rg = tid >> 3;         // rows   [rg*8, rg*8+8)
    const float* whp = whS + fg * 8;
    const float* pp  = pS  + rg * 8;

    u64 acc[32];
#pragma unroll
    for (int k = 0; k < 32; k++) acc[k] = 0ull;

    __syncthreads();

    for (int t = 0; t < NTILE; t++) {
        // stage Wh tile (32 j x 64 feats)
        {
            const float4* src = (const float4*)(g_Wh + ((size_t)(b*NN + j0 + t*TJ)) * FOUT);
            float4* dst = (float4*)whS;
            dst[tid]       = src[tid];
            dst[tid + 256] = src[tid + 256];
        }
        // phase A: P[j][i] numerators (no max shift needed; |e| <~ 20)
        {
            unsigned word = bitsS[tid * 17 + t];
#pragma unroll
            for (int jj = 0; jj < TJ; jj++) {
                float e = s1r + s2S[t*TJ + jj];
                float l = fmaxf(e, ALPHA * e);
                float p = ((word >> jj) & 1u) ? __expf(l) : 0.f;
                pS[jj*MC + tid] = p;
            }
        }
        __syncthreads();

        // phase B: 8x8 register tile, f32x2
#pragma unroll 8
        for (int jj = 0; jj < TJ; jj++) {
            const float4* wv = (const float4*)(whp + jj*FOUT);
            float4 wa = wv[0];
            float4 wb = wv[1];
            const ulonglong2* pv2 = (const ulonglong2*)(pp + jj*MC);
            ulonglong2 pA = pv2[0];
            ulonglong2 pB = pv2[1];
            u64 w;
            w = dup2(wa.x); acc[0] =ffma2(w,pA.x,acc[0]);  acc[1] =ffma2(w,pA.y,acc[1]);  acc[2] =ffma2(w,pB.x,acc[2]);  acc[3] =ffma2(w,pB.y,acc[3]);
            w = dup2(wa.y); acc[4] =ffma2(w,pA.x,acc[4]);  acc[5] =ffma2(w,pA.y,acc[5]);  acc[6] =ffma2(w,pB.x,acc[6]);  acc[7] =ffma2(w,pB.y,acc[7]);
            w = dup2(wa.z); acc[8] =ffma2(w,pA.x,acc[8]);  acc[9] =ffma2(w,pA.y,acc[9]);  acc[10]=ffma2(w,pB.x,acc[10]); acc[11]=ffma2(w,pB.y,acc[11]);
            w = dup2(wa.w); acc[12]=ffma2(w,pA.x,acc[12]); acc[13]=ffma2(w,pA.y,acc[13]); acc[14]=ffma2(w,pB.x,acc[14]); acc[15]=ffma2(w,pB.y,acc[15]);
            w = dup2(wb.x); acc[16]=ffma2(w,pA.x,acc[16]); acc[17]=ffma2(w,pA.y,acc[17]); acc[18]=ffma2(w,pB.x,acc[18]); acc[19]=ffma2(w,pB.y,acc[19]);
            w = dup2(wb.y); acc[20]=ffma2(w,pA.x,acc[20]); acc[21]=ffma2(w,pA.y,acc[21]); acc[22]=ffma2(w,pB.x,acc[22]); acc[23]=ffma2(w,pB.y,acc[23]);
            w = dup2(wb.z); acc[24]=ffma2(w,pA.x,acc[24]); acc[25]=ffma2(w,pA.y,acc[25]); acc[26]=ffma2(w,pB.x,acc[26]); acc[27]=ffma2(w,pB.y,acc[27]);
            w = dup2(wb.w); acc[28]=ffma2(w,pA.x,acc[28]); acc[29]=ffma2(w,pA.y,acc[29]); acc[30]=ffma2(w,pB.x,acc[30]); acc[31]=ffma2(w,pB.y,acc[31]);
        }
        __syncthreads();
    }

    // epilogue: atomic partial-sum into g_acc
    float* obase = g_acc + ((size_t)(b*NN + i0 + rg*8)) * FOUT + fg*8;
#pragma unroll
    for (int q = 0; q < 4; q++) {
        float4 lo0 = make_float4(lo32(acc[0*4+q]), lo32(acc[1*4+q]), lo32(acc[2*4+q]), lo32(acc[3*4+q]));
        float4 lo1 = make_float4(lo32(acc[4*4+q]), lo32(acc[5*4+q]), lo32(acc[6*4+q]), lo32(acc[7*4+q]));
        float4 hi0 = make_float4(hi32(acc[0*4+q]), hi32(acc[1*4+q]), hi32(acc[2*4+q]), hi32(acc[3*4+q]));
        float4 hi1 = make_float4(hi32(acc[4*4+q]), hi32(acc[5*4+q]), hi32(acc[6*4+q]), hi32(acc[7*4+q]));
        float* r0p = obase + (size_t)(2*q) * FOUT;
        float* r1p = obase + (size_t)(2*q + 1) * FOUT;
        atomicAdd((float4*)r0p,       lo0);
        atomicAdd((float4*)(r0p + 4), lo1);
        atomicAdd((float4*)r1p,       hi0);
        atomicAdd((float4*)(r1p + 4), hi1);
    }
}

// ---------------- K5: normalize + ELU -------------------------------------
__global__ void k_final(float* __restrict__ out) {
    int idx = blockIdx.x * 256 + threadIdx.x;     // float4 index
    float4 v = ((const float4*)g_acc)[idx];
    int row = idx >> 4;                            // 16 float4 per row
    float inv = 1.f / g_Z[row];
    float4 o;
    o.x = elu1(v.x * inv);
    o.y = elu1(v.y * inv);
    o.z = elu1(v.z * inv);
    o.w = elu1(v.w * inv);
    ((float4*)out)[idx] = o;
}

// ---------------- launch --------------------------------------------------
extern "C" void kernel_launch(void* const* d_in, const int* in_sizes, int n_in,
                              void* d_out, int out_size) {
    const float* h   = (const float*)d_in[0];
    const int*   adj = (const int*)  d_in[1];
    const float* W   = (const float*)d_in[2];
    const float* a   = (const float*)d_in[3];
    float* out = (float*)d_out;

    cudaFuncSetAttribute(k_main, cudaFuncAttributeMaxDynamicSharedMemorySize, SMEM_MAIN);

    k_proj <<<(BB*NN)/4, 256>>>(h, W, a);
    k_prep <<<NN/4, 256>>>(adj);
    k_zero <<<(BB*NN*FOUT)/(4*256), 256>>>();
    k_main <<<dim3(NN/MC, S_SPLIT, BB), 256, SMEM_MAIN>>>();
    k_final<<<(BB*NN*FOUT)/(4*256), 256>>>(out);
}

// round 6
// speedup vs baseline: 3.5074x; 2.3026x over previous
#include <cuda_runtime.h>
#include <math.h>
#include <stdint.h>

#define NN     4096
#define BB     2
#define FIN    128
#define FOUT   64
#define NW     128
#define ALPHA  0.2f

#define SPLITS  2
#define KR      (NN/SPLITS)     // 2048 k per CTA
#define NT      32              // tiles of 64 k

// k_main smem byte offsets
#define BITSB  8192
#define BSTR   68               // bits row stride (words), bank-spread + 16B aligned
#define BBUFB  (BITSB + 128*BSTR*4)        // 43008
#define SMEMB  (BBUFB + 2*1024*16)         // 75776

__device__ float    g_s1[BB*NN];
__device__ float    g_s2[BB*NN];
__device__ float    g_Z [BB*NN];
__device__ unsigned g_adjbits[NN*NW];
__device__ uint4    g_WhF4[BB*65536];     // Wh in B-fragment order, tf32-rounded
__device__ float    g_acc0[BB*NN*FOUT];
__device__ float    g_acc1[BB*NN*FOUT];

__device__ __forceinline__ float elu1(float v) { return v > 0.f ? v : expm1f(v); }
__device__ __forceinline__ unsigned tf32r(float x) {
    unsigned u;
    asm("cvt.rna.tf32.f32 %0, %1;" : "=r"(u) : "f"(x));
    return u;
}
__device__ __forceinline__ void mma8(float* c, unsigned a0, unsigned a1,
                                     unsigned a2, unsigned a3,
                                     unsigned b0, unsigned b1) {
    asm volatile("mma.sync.aligned.m16n8k8.row.col.f32.tf32.tf32.f32 "
        "{%0,%1,%2,%3}, {%4,%5,%6,%7}, {%8,%9}, {%0,%1,%2,%3};"
        : "+f"(c[0]), "+f"(c[1]), "+f"(c[2]), "+f"(c[3])
        : "r"(a0), "r"(a1), "r"(a2), "r"(a3), "r"(b0), "r"(b1));
}
__device__ __forceinline__ float pexp(float e, unsigned bit) {
    float l = fmaxf(e, ALPHA * e);
    float p = __expf(l);
    return bit ? p : 0.f;
}

// ---------------- K1: Wh (fragment layout) + s1 + s2 -----------------------
__global__ __launch_bounds__(256) void k_proj(const float* __restrict__ h,
                                              const float* __restrict__ W,
                                              const float* __restrict__ a) {
    __shared__ float  Ws[FIN*FOUT];
    __shared__ float  hS[16*FIN];
    __shared__ float2 sred[8];
    int tid = threadIdx.x;
    {
        const float4* w4 = (const float4*)W;
        float4* d4 = (float4*)Ws;
#pragma unroll
        for (int k = 0; k < 8; k++) d4[tid + k*256] = w4[tid + k*256];
    }
    int rowbase = blockIdx.x * 16;
    {
        const float4* h4 = (const float4*)(h + (size_t)rowbase * FIN);
        float4* d4 = (float4*)hS;
        d4[tid] = h4[tid]; d4[tid+256] = h4[tid+256];
    }
    __syncthreads();

    int o = tid & 63, r4 = tid >> 6, wid = tid >> 5;
    unsigned* whf = (unsigned*)g_WhF4;
    for (int g = 0; g < 4; g++) {
        if (g) __syncthreads();
        int rl = g*4 + r4;
        float acc = 0.f;
        const float4* h4 = (const float4*)(hS + rl * FIN);
#pragma unroll
        for (int f4 = 0; f4 < FIN/4; f4++) {
            float4 hv = h4[f4];
            acc = fmaf(hv.x, Ws[(f4*4+0)*FOUT + o], acc);
            acc = fmaf(hv.y, Ws[(f4*4+1)*FOUT + o], acc);
            acc = fmaf(hv.z, Ws[(f4*4+2)*FOUT + o], acc);
            acc = fmaf(hv.w, Ws[(f4*4+3)*FOUT + o], acc);
        }
        int gr = rowbase + rl;
        int bb = gr >> 12, k = gr & (NN-1);
        // B-fragment scatter: f4i = ((k/16)*8 + o/8)*32 + (o%8)*4 + k%4 ; slot q=(k%16)/4
        int f4i = ((k >> 4)*8 + (o >> 3))*32 + ((o & 7)*4 + (k & 3));
        int q   = (k >> 2) & 3;
        whf[(size_t)bb*262144 + (size_t)f4i*4 + q] = tf32r(acc);

        float p1 = acc * __ldg(a + o);
        float p2 = acc * __ldg(a + FOUT + o);
#pragma unroll
        for (int off = 16; off; off >>= 1) {
            p1 += __shfl_xor_sync(0xffffffffu, p1, off);
            p2 += __shfl_xor_sync(0xffffffffu, p2, off);
        }
        if ((tid & 31) == 0) sred[wid] = make_float2(p1, p2);
        __syncthreads();
        if (tid < 4) {
            float2 x = sred[tid*2], y = sred[tid*2+1];
            g_s1[rowbase + g*4 + tid] = x.x + y.x;
            g_s2[rowbase + g*4 + tid] = x.y + y.y;
        }
    }
}

// ---------------- K2: warp-per-row pack + Z --------------------------------
__global__ __launch_bounds__(256) void k_prep(const int* __restrict__ adj) {
    __shared__ float s2S[2*NN];    // 32 KB
    int tid = threadIdx.x, lane = tid & 31, wid = tid >> 5;
    for (int k = tid; k < (2*NN)/4; k += 256)
        ((float4*)s2S)[k] = ((const float4*)g_s2)[k];
    __syncthreads();

    int i = blockIdx.x * 8 + wid;
    float s10 = g_s1[i], s11 = g_s1[NN + i];
    const int* arow = adj + (size_t)i * NN;
    float z0 = 0.f, z1 = 0.f;
#pragma unroll
    for (int q = 0; q < 4; q++) {
        unsigned myw = 0;
#pragma unroll 4
        for (int s = 0; s < 32; s++) {
            int j32 = q*1024 + s*32;
            int v = arow[j32 + lane];
            unsigned on = v > 0;
            unsigned bal = __ballot_sync(0xffffffffu, on);
            if (s == lane) myw = bal;
            z0 += pexp(s10 + s2S[j32 + lane], on);
            z1 += pexp(s11 + s2S[NN + j32 + lane], on);
        }
        g_adjbits[(size_t)i * NW + q*32 + lane] = myw;
    }
#pragma unroll
    for (int off = 16; off; off >>= 1) {
        z0 += __shfl_xor_sync(0xffffffffu, z0, off);
        z1 += __shfl_xor_sync(0xffffffffu, z1, off);
    }
    if (lane == 0) { g_Z[i] = z0; g_Z[NN + i] = z1; }
}

// ---------------- K3: mma.sync tf32 GEMM, K-split --------------------------
// Grid (32 rowtiles, 2 ksplits, 2 batches). 8 warps x 16 exclusive rows.
__global__ __launch_bounds__(256) void k_main() {
    extern __shared__ char smem[];
    float*    s2S   = (float*)smem;                 // 2048 f
    unsigned* bitsS = (unsigned*)(smem + BITSB);    // 128 x BSTR
    uint4*    Bbuf  = (uint4*)(smem + BBUFB);       // 2 x 1024 uint4

    int tid = threadIdx.x, lane = tid & 31, wid = tid >> 5;
    int b = blockIdx.z, split = blockIdx.y;
    int i0 = blockIdx.x * 128;
    int kbase = split * KR;

    // stage s2 chunk (2048 floats)
    {
        const float4* src = (const float4*)(g_s2 + b*NN + kbase);
        float4* dst = (float4*)s2S;
        dst[tid] = src[tid]; dst[tid + 256] = src[tid + 256];
    }
    // stage bits: 128 rows x 64 words
    {
        int row = tid >> 1, hh = tid & 1;
        const uint4* src = (const uint4*)(g_adjbits + (size_t)(i0+row)*NW + split*64 + hh*32);
        uint4* dst = (uint4*)(bitsS + row*BSTR + hh*32);
#pragma unroll
        for (int q = 0; q < 8; q++) dst[q] = src[q];
    }
    const uint4* srcB = g_WhF4 + (size_t)b * 65536;
    // preload tile 0
    {
        const uint4* s = srcB + (size_t)(split*128) * 256;
#pragma unroll
        for (int j = 0; j < 4; j++) Bbuf[tid + j*256] = __ldg(s + tid + j*256);
    }
    int r0l = wid*16 + (lane >> 2);
    float s1r0 = g_s1[b*NN + i0 + r0l];
    float s1r1 = g_s1[b*NN + i0 + r0l + 8];
    const unsigned* bw0 = bitsS + r0l * BSTR;
    const unsigned* bw1 = bitsS + (r0l + 8) * BSTR;
    __syncthreads();

    float acc[8][4];
#pragma unroll
    for (int nt = 0; nt < 8; nt++)
#pragma unroll
        for (int c = 0; c < 4; c++) acc[nt][c] = 0.f;

    for (int t = 0; t < NT; t++) {
        int cur = t & 1;
        uint4 st0, st1, st2, st3;
        if (t + 1 < NT) {
            const uint4* s = srcB + (size_t)(split*128 + (t+1)*4) * 256;
            st0 = __ldg(s + tid);       st1 = __ldg(s + tid + 256);
            st2 = __ldg(s + tid + 512); st3 = __ldg(s + tid + 768);
        }
        const uint4* bb4 = Bbuf + cur*1024;
        unsigned w0  = bw0[2*t], w0b = bw0[2*t + 1];
        unsigned w1  = bw1[2*t], w1b = bw1[2*t + 1];
        uint4 bq[8];
#pragma unroll
        for (int kk = 0; kk < 8; kk++) {
            int kl = t*64 + kk*8 + (lane & 3);
            float s2a = s2S[kl], s2b = s2S[kl + 4];
            unsigned wa = (kk < 4) ? w0 : w0b;
            unsigned wb = (kk < 4) ? w1 : w1b;
            int pos = ((kk & 3) << 3) + (lane & 3);
            unsigned a0 = tf32r(pexp(s1r0 + s2a, (wa >> pos) & 1u));
            unsigned a1 = tf32r(pexp(s1r1 + s2a, (wb >> pos) & 1u));
            unsigned a2 = tf32r(pexp(s1r0 + s2b, (wa >> (pos+4)) & 1u));
            unsigned a3 = tf32r(pexp(s1r1 + s2b, (wb >> (pos+4)) & 1u));
            if ((kk & 1) == 0) {
#pragma unroll
                for (int nt = 0; nt < 8; nt++)
                    bq[nt] = bb4[(kk >> 1)*256 + nt*32 + lane];
            }
#pragma unroll
            for (int nt = 0; nt < 8; nt++) {
                unsigned bx = (kk & 1) ? bq[nt].z : bq[nt].x;
                unsigned by = (kk & 1) ? bq[nt].w : bq[nt].y;
                mma8(acc[nt], a0, a1, a2, a3, bx, by);
            }
        }
        if (t + 1 < NT) {
            uint4* d = Bbuf + (cur^1)*1024;
            d[tid] = st0; d[tid+256] = st1; d[tid+512] = st2; d[tid+768] = st3;
        }
        __syncthreads();
    }

    // epilogue: write split partials
    float* accp = (split == 0 ? g_acc0 : g_acc1) + ((size_t)(b*NN + i0 + r0l)) * FOUT;
#pragma unroll
    for (int nt = 0; nt < 8; nt++) {
        int col = nt*8 + 2*(lane & 3);
        *(float2*)(accp + col)            = make_float2(acc[nt][0], acc[nt][1]);
        *(float2*)(accp + 8*FOUT + col)   = make_float2(acc[nt][2], acc[nt][3]);
    }
}

// ---------------- K4: combine splits, normalize, ELU -----------------------
__global__ void k_final(float* __restrict__ out) {
    int idx = blockIdx.x * 256 + threadIdx.x;
    float4 v0 = ((const float4*)g_acc0)[idx];
    float4 v1 = ((const float4*)g_acc1)[idx];
    int row = idx >> 4;
    float inv = 1.f / g_Z[row];
    float4 o;
    o.x = elu1((v0.x + v1.x) * inv);
    o.y = elu1((v0.y + v1.y) * inv);
    o.z = elu1((v0.z + v1.z) * inv);
    o.w = elu1((v0.w + v1.w) * inv);
    ((float4*)out)[idx] = o;
}

// ---------------- launch ---------------------------------------------------
extern "C" void kernel_launch(void* const* d_in, const int* in_sizes, int n_in,
                              void* d_out, int out_size) {
    const float* h   = (const float*)d_in[0];
    const int*   adj = (const int*)  d_in[1];
    const float* W   = (const float*)d_in[2];
    const float* a   = (const float*)d_in[3];
    float* out = (float*)d_out;

    cudaFuncSetAttribute(k_main, cudaFuncAttributeMaxDynamicSharedMemorySize, SMEMB);

    k_proj <<<(BB*NN)/16, 256>>>(h, W, a);
    k_prep <<<NN/8, 256>>>(adj);
    k_main <<<dim3(NN/128, SPLITS, BB), 256, SMEMB>>>();
    k_final<<<(BB*NN*FOUT)/(4*256), 256>>>(out);
}

// round 8
// speedup vs baseline: 3.9880x; 1.1370x over previous
#include <cuda_runtime.h>
#include <math.h>
#include <stdint.h>

#define NN     4096
#define BB     2
#define FIN    128
#define FOUT   64
#define NW     128
#define ALPHA  0.2f

#define SPLITS  4
#define KR      (NN/SPLITS)     // 1024 k per CTA
#define NT      16              // tiles of 64 k

// k_main smem byte offsets
#define BITSB  4096
#define BSTR   36               // 32 words + pad (144B rows, 16B aligned)
#define BBUFB  (BITSB + 128*BSTR*4)        // 22528
#define SMEMB  (BBUFB + 2*1024*16)         // 55296

__device__ float    g_s1[BB*NN];
__device__ float    g_s2[BB*NN];
__device__ float    g_Zp[SPLITS*BB*NN];
__device__ unsigned g_adjbits[NN*NW];
__device__ uint4    g_WhF4[BB*65536];     // Wh in B-fragment order, tf32-rounded
__device__ float    g_acc0[BB*NN*FOUT];
__device__ float    g_acc1[BB*NN*FOUT];
__device__ float    g_acc2[BB*NN*FOUT];
__device__ float    g_acc3[BB*NN*FOUT];

__device__ __forceinline__ float elu1(float v) { return v > 0.f ? v : expm1f(v); }
__device__ __forceinline__ unsigned tf32r(float x) {
    unsigned u;
    asm("cvt.rna.tf32.f32 %0, %1;" : "=r"(u) : "f"(x));
    return u;
}
__device__ __forceinline__ void mma8(float* c, unsigned a0, unsigned a1,
                                     unsigned a2, unsigned a3,
                                     unsigned b0, unsigned b1) {
    asm volatile("mma.sync.aligned.m16n8k8.row.col.f32.tf32.tf32.f32 "
        "{%0,%1,%2,%3}, {%4,%5,%6,%7}, {%8,%9}, {%0,%1,%2,%3};"
        : "+f"(c[0]), "+f"(c[1]), "+f"(c[2]), "+f"(c[3])
        : "r"(a0), "r"(a1), "r"(a2), "r"(a3), "r"(b0), "r"(b1));
}
__device__ __forceinline__ float pexp(float e, unsigned bit) {
    float l = fmaxf(e, ALPHA * e);
    float p = __expf(l);
    return bit ? p : 0.f;
}

// ---------------- K1: Wh (fragment layout) + s1 + s2 + adj pack ------------
__global__ __launch_bounds__(256) void k_proj(const float* __restrict__ h,
                                              const float* __restrict__ W,
                                              const float* __restrict__ a,
                                              const int* __restrict__ adj) {
    __shared__ float  Ws[FIN*FOUT];
    __shared__ float  hS[16*FIN];
    __shared__ float2 sred[8];
    int tid = threadIdx.x, lane = tid & 31, wid = tid >> 5;
    {
        const float4* w4 = (const float4*)W;
        float4* d4 = (float4*)Ws;
#pragma unroll
        for (int k = 0; k < 8; k++) d4[tid + k*256] = w4[tid + k*256];
    }
    int rowbase = blockIdx.x * 16;
    {
        const float4* h4 = (const float4*)(h + (size_t)rowbase * FIN);
        float4* d4 = (float4*)hS;
        d4[tid] = h4[tid]; d4[tid+256] = h4[tid+256];
    }
    __syncthreads();

    int o = tid & 63, r4 = tid >> 6;
    unsigned* whf = (unsigned*)g_WhF4;
    for (int g = 0; g < 4; g++) {
        if (g) __syncthreads();
        int rl = g*4 + r4;
        float acc = 0.f;
        const float4* h4 = (const float4*)(hS + rl * FIN);
#pragma unroll
        for (int f4 = 0; f4 < FIN/4; f4++) {
            float4 hv = h4[f4];
            acc = fmaf(hv.x, Ws[(f4*4+0)*FOUT + o], acc);
            acc = fmaf(hv.y, Ws[(f4*4+1)*FOUT + o], acc);
            acc = fmaf(hv.z, Ws[(f4*4+2)*FOUT + o], acc);
            acc = fmaf(hv.w, Ws[(f4*4+3)*FOUT + o], acc);
        }
        int gr = rowbase + rl;
        int bb = gr >> 12, k = gr & (NN-1);
        int f4i = ((k >> 4)*8 + (o >> 3))*32 + ((o & 7)*4 + (k & 3));
        int q   = (k >> 2) & 3;
        whf[(size_t)bb*262144 + (size_t)f4i*4 + q] = tf32r(acc);

        float p1 = acc * __ldg(a + o);
        float p2 = acc * __ldg(a + FOUT + o);
#pragma unroll
        for (int off = 16; off; off >>= 1) {
            p1 += __shfl_xor_sync(0xffffffffu, p1, off);
            p2 += __shfl_xor_sync(0xffffffffu, p2, off);
        }
        if ((tid & 31) == 0) sred[wid] = make_float2(p1, p2);
        __syncthreads();
        if (tid < 4) {
            float2 x = sred[tid*2], y = sred[tid*2+1];
            g_s1[rowbase + g*4 + tid] = x.x + y.x;
            g_s2[rowbase + g*4 + tid] = x.y + y.y;
        }
    }

    // ---- adj pack: 8 rows per CTA, warp-per-row -----------------------------
    {
        int prow = blockIdx.x * 8 + wid;     // grid 512 * 8 = 4096 rows
        const int* arow = adj + (size_t)prow * NN;
#pragma unroll
        for (int q = 0; q < 4; q++) {
            unsigned myw = 0;
#pragma unroll 4
            for (int s = 0; s < 32; s++) {
                unsigned bal = __ballot_sync(0xffffffffu, arow[q*1024 + s*32 + lane] > 0);
                if (s == lane) myw = bal;
            }
            g_adjbits[(size_t)prow * NW + q*32 + lane] = myw;
        }
    }
}

// ---------------- K2: mma.sync tf32 GEMM, K-split 4, fused Z ---------------
// Grid (32 rowtiles, 4 ksplits, 2 batches). 8 warps x 16 exclusive rows.
__global__ __launch_bounds__(256, 2) void k_main() {
    extern __shared__ char smem[];
    float*    s2S   = (float*)smem;                 // KR floats
    unsigned* bitsS = (unsigned*)(smem + BITSB);    // 128 x BSTR
    uint4*    Bbuf  = (uint4*)(smem + BBUFB);       // 2 x 1024 uint4

    int tid = threadIdx.x, lane = tid & 31, wid = tid >> 5;
    int b = blockIdx.z, split = blockIdx.y;
    int i0 = blockIdx.x * 128;
    int kbase = split * KR;

    // stage s2 chunk (KR floats)
    ((float4*)s2S)[tid] = ((const float4*)(g_s2 + b*NN + kbase))[tid];
    // stage bits: 128 rows x 32 words
    {
        int row = tid >> 1, hh = tid & 1;
        const uint4* src = (const uint4*)(g_adjbits + (size_t)(i0+row)*NW + (kbase >> 5) + hh*16);
        uint4* dst = (uint4*)(bitsS + row*BSTR + hh*16);
#pragma unroll
        for (int q = 0; q < 4; q++) dst[q] = src[q];
    }
    const uint4* srcB = g_WhF4 + (size_t)b * 65536;
    // preload tile 0
    {
        const uint4* s = srcB + (size_t)(kbase >> 4) * 256;
#pragma unroll
        for (int j = 0; j < 4; j++) Bbuf[tid + j*256] = __ldg(s + tid + j*256);
    }
    int r0l = wid*16 + (lane >> 2);
    float s1r0 = g_s1[b*NN + i0 + r0l];
    float s1r1 = g_s1[b*NN + i0 + r0l + 8];
    const unsigned* bw0 = bitsS + r0l * BSTR;
    const unsigned* bw1 = bitsS + (r0l + 8) * BSTR;
    __syncthreads();

    float acc[8][4];
#pragma unroll
    for (int nt = 0; nt < 8; nt++)
#pragma unroll
        for (int c = 0; c < 4; c++) acc[nt][c] = 0.f;
    float z0 = 0.f, z1 = 0.f;

    for (int t = 0; t < NT; t++) {
        int cur = t & 1;
        uint4 st0, st1, st2, st3;
        if (t + 1 < NT) {
            const uint4* s = srcB + (size_t)((kbase >> 4) + (t+1)*4) * 256;
            st0 = __ldg(s + tid);       st1 = __ldg(s + tid + 256);
            st2 = __ldg(s + tid + 512); st3 = __ldg(s + tid + 768);
        }
        const uint4* bb4 = Bbuf + cur*1024;
        unsigned w0  = bw0[2*t], w0b = bw0[2*t + 1];
        unsigned w1  = bw1[2*t], w1b = bw1[2*t + 1];
        uint4 bq[8];
#pragma unroll
        for (int kk = 0; kk < 8; kk++) {
            int kl = t*64 + kk*8 + (lane & 3);
            float s2a = s2S[kl], s2b = s2S[kl + 4];
            unsigned wa = (kk < 4) ? w0 : w0b;
            unsigned wb = (kk < 4) ? w1 : w1b;
            int pos = ((kk & 3) << 3) + (lane & 3);
            float p0 = pexp(s1r0 + s2a, (wa >> pos) & 1u);
            float p1 = pexp(s1r1 + s2a, (wb >> pos) & 1u);
            float p2 = pexp(s1r0 + s2b, (wa >> (pos+4)) & 1u);
            float p3 = pexp(s1r1 + s2b, (wb >> (pos+4)) & 1u);
            z0 += p0 + p2;
            z1 += p1 + p3;
            unsigned a0 = tf32r(p0), a1 = tf32r(p1), a2 = tf32r(p2), a3 = tf32r(p3);
            if ((kk & 1) == 0) {
#pragma unroll
                for (int nt = 0; nt < 8; nt++)
                    bq[nt] = bb4[(kk >> 1)*256 + nt*32 + lane];
            }
#pragma unroll
            for (int nt = 0; nt < 8; nt++) {
                unsigned bx = (kk & 1) ? bq[nt].z : bq[nt].x;
                unsigned by = (kk & 1) ? bq[nt].w : bq[nt].y;
                mma8(acc[nt], a0, a1, a2, a3, bx, by);
            }
        }
        if (t + 1 < NT) {
            uint4* d = Bbuf + (cur^1)*1024;
            d[tid] = st0; d[tid+256] = st1; d[tid+512] = st2; d[tid+768] = st3;
        }
        __syncthreads();
    }

    // Z partials: reduce over the 4 lanes of each quad (deterministic)
    z0 += __shfl_xor_sync(0xffffffffu, z0, 1);
    z0 += __shfl_xor_sync(0xffffffffu, z0, 2);
    z1 += __shfl_xor_sync(0xffffffffu, z1, 1);
    z1 += __shfl_xor_sync(0xffffffffu, z1, 2);
    if ((lane & 3) == 0) {
        g_Zp[split*BB*NN + b*NN + i0 + r0l]     = z0;
        g_Zp[split*BB*NN + b*NN + i0 + r0l + 8] = z1;
    }

    // write split partials
    float* accp = (split == 0 ? g_acc0 : split == 1 ? g_acc1 :
                   split == 2 ? g_acc2 : g_acc3)
                  + ((size_t)(b*NN + i0 + r0l)) * FOUT;
#pragma unroll
    for (int nt = 0; nt < 8; nt++) {
        int col = nt*8 + 2*(lane & 3);
        *(float2*)(accp + col)            = make_float2(acc[nt][0], acc[nt][1]);
        *(float2*)(accp + 8*FOUT + col)   = make_float2(acc[nt][2], acc[nt][3]);
    }
}

// ---------------- K3: combine splits, normalize, ELU -----------------------
__global__ void k_final(float* __restrict__ out) {
    int idx = blockIdx.x * 256 + threadIdx.x;
    float4 v0 = ((const float4*)g_acc0)[idx];
    float4 v1 = ((const float4*)g_acc1)[idx];
    float4 v2 = ((const float4*)g_acc2)[idx];
    float4 v3 = ((const float4*)g_acc3)[idx];
    int row = idx >> 4;
    float Z = g_Zp[row] + g_Zp[BB*NN + row] + g_Zp[2*BB*NN + row] + g_Zp[3*BB*NN + row];
    float inv = 1.f / Z;
    float4 o;
    o.x = elu1((v0.x + v1.x + v2.x + v3.x) * inv);
    o.y = elu1((v0.y + v1.y + v2.y + v3.y) * inv);
    o.z = elu1((v0.z + v1.z + v2.z + v3.z) * inv);
    o.w = elu1((v0.w + v1.w + v2.w + v3.w) * inv);
    ((float4*)out)[idx] = o;
}

// ---------------- launch ---------------------------------------------------
extern "C" void kernel_launch(void* const* d_in, const int* in_sizes, int n_in,
                              void* d_out, int out_size) {
    const float* h   = (const float*)d_in[0];
    const int*   adj = (const int*)  d_in[1];
    const float* W   = (const float*)d_in[2];
    const float* a   = (const float*)d_in[3];
    float* out = (float*)d_out;

    cudaFuncSetAttribute(k_main, cudaFuncAttributeMaxDynamicSharedMemorySize, SMEMB);

    k_proj <<<(BB*NN)/16, 256>>>(h, W, a, adj);
    k_main <<<dim3(NN/128, SPLITS, BB), 256, SMEMB>>>();
    k_final<<<(BB*NN*FOUT)/(4*256), 256>>>(out);
}

// round 9
// speedup vs baseline: 4.1025x; 1.0287x over previous
#include <cuda_runtime.h>
#include <math.h>
#include <stdint.h>

#define NN     4096
#define BB     2
#define FIN    128
#define FOUT   64
#define NW     128
#define ALPHA  0.2f

#define SPLITS  4
#define KR      (NN/SPLITS)     // 1024 k per CTA
#define NT      16              // tiles of 64 k

// k_main smem byte offsets
#define BITSB  4096
#define BSTR   36               // 32 words + pad (144B rows, 16B aligned)
#define BBUFB  (BITSB + 128*BSTR*4)        // 22528
#define SMEMB  (BBUFB + 2*1024*16)         // 55296

__device__ float    g_s1[BB*NN];
__device__ float    g_s2[BB*NN];
__device__ float    g_Zp[SPLITS*BB*NN];
__device__ unsigned g_adjbits[NN*NW];
__device__ uint4    g_WhF4[BB*65536];     // Wh in B-fragment order, tf32-rounded
__device__ float    g_acc0[BB*NN*FOUT];
__device__ float    g_acc1[BB*NN*FOUT];
__device__ float    g_acc2[BB*NN*FOUT];
__device__ float    g_acc3[BB*NN*FOUT];

__device__ __forceinline__ float elu1(float v) { return v > 0.f ? v : expm1f(v); }
__device__ __forceinline__ unsigned tf32r(float x) {
    unsigned u;
    asm("cvt.rna.tf32.f32 %0, %1;" : "=r"(u) : "f"(x));
    return u;
}
__device__ __forceinline__ void mma8(float* c, unsigned a0, unsigned a1,
                                     unsigned a2, unsigned a3,
                                     unsigned b0, unsigned b1) {
    asm volatile("mma.sync.aligned.m16n8k8.row.col.f32.tf32.tf32.f32 "
        "{%0,%1,%2,%3}, {%4,%5,%6,%7}, {%8,%9}, {%0,%1,%2,%3};"
        : "+f"(c[0]), "+f"(c[1]), "+f"(c[2]), "+f"(c[3])
        : "r"(a0), "r"(a1), "r"(a2), "r"(a3), "r"(b0), "r"(b1));
}
__device__ __forceinline__ float pexp(float e, unsigned bit) {
    float l = fmaxf(e, ALPHA * e);
    float p = __expf(l);
    return bit ? p : 0.f;
}
__device__ __forceinline__ int ldcs_i(const int* p) {
    int v;
    asm volatile("ld.global.cs.b32 %0, [%1];" : "=r"(v) : "l"(p));
    return v;
}

// ---------------- K1: Wh (fragment layout) + s1 + s2 + adj pack ------------
__global__ __launch_bounds__(256) void k_proj(const float* __restrict__ h,
                                              const float* __restrict__ W,
                                              const float* __restrict__ a,
                                              const int* __restrict__ adj) {
    __shared__ float  Ws[FIN*FOUT];
    __shared__ float  hS[16*FIN];
    __shared__ float2 sred[8];
    int tid = threadIdx.x, lane = tid & 31, wid = tid >> 5;
    {
        const float4* w4 = (const float4*)W;
        float4* d4 = (float4*)Ws;
#pragma unroll
        for (int k = 0; k < 8; k++) d4[tid + k*256] = w4[tid + k*256];
    }
    int rowbase = blockIdx.x * 16;
    {
        const float4* h4 = (const float4*)(h + (size_t)rowbase * FIN);
        float4* d4 = (float4*)hS;
        d4[tid] = h4[tid]; d4[tid+256] = h4[tid+256];
    }
    __syncthreads();

    int o = tid & 63, r4 = tid >> 6;
    unsigned* whf = (unsigned*)g_WhF4;
    for (int g = 0; g < 4; g++) {
        if (g) __syncthreads();
        int rl = g*4 + r4;
        float acc = 0.f;
        const float4* h4 = (const float4*)(hS + rl * FIN);
#pragma unroll
        for (int f4 = 0; f4 < FIN/4; f4++) {
            float4 hv = h4[f4];
            acc = fmaf(hv.x, Ws[(f4*4+0)*FOUT + o], acc);
            acc = fmaf(hv.y, Ws[(f4*4+1)*FOUT + o], acc);
            acc = fmaf(hv.z, Ws[(f4*4+2)*FOUT + o], acc);
            acc = fmaf(hv.w, Ws[(f4*4+3)*FOUT + o], acc);
        }
        int gr = rowbase + rl;
        int bb = gr >> 12, k = gr & (NN-1);
        int f4i = ((k >> 4)*8 + (o >> 3))*32 + ((o & 7)*4 + (k & 3));
        int q   = (k >> 2) & 3;
        whf[(size_t)bb*262144 + (size_t)f4i*4 + q] = tf32r(acc);

        float p1 = acc * __ldg(a + o);
        float p2 = acc * __ldg(a + FOUT + o);
#pragma unroll
        for (int off = 16; off; off >>= 1) {
            p1 += __shfl_xor_sync(0xffffffffu, p1, off);
            p2 += __shfl_xor_sync(0xffffffffu, p2, off);
        }
        if ((tid & 31) == 0) sred[wid] = make_float2(p1, p2);
        __syncthreads();
        if (tid < 4) {
            float2 x = sred[tid*2], y = sred[tid*2+1];
            g_s1[rowbase + g*4 + tid] = x.x + y.x;
            g_s2[rowbase + g*4 + tid] = x.y + y.y;
        }
    }

    // ---- adj pack: warp-per-row, prefetch-16 then ballot (MLP=16) ----------
    {
        int prow = blockIdx.x * 8 + wid;     // grid 512 * 8 = 4096 rows
        const int* arow = adj + (size_t)prow * NN;
#pragma unroll
        for (int q = 0; q < 8; q++) {
            int v[16];
#pragma unroll
            for (int s = 0; s < 16; s++)
                v[s] = ldcs_i(arow + q*512 + s*32 + lane);
            unsigned myw = 0;
#pragma unroll
            for (int s = 0; s < 16; s++) {
                unsigned bal = __ballot_sync(0xffffffffu, v[s] > 0);
                if ((lane & 15) == s) myw = bal;
            }
            // lanes 0..15 hold words for first half-q, 16..31 duplicate; write 16
            if ((lane >> 4) == 0)
                g_adjbits[(size_t)prow * NW + q*16 + lane] = myw;
        }
    }
}

// ---------------- K2: mma.sync tf32 GEMM, K-split 4, fused Z ---------------
// Grid (32 rowtiles, 4 ksplits, 2 batches). 8 warps x 16 exclusive rows.
__global__ __launch_bounds__(256, 2) void k_main() {
    extern __shared__ char smem[];
    float*    s2S   = (float*)smem;                 // KR floats
    unsigned* bitsS = (unsigned*)(smem + BITSB);    // 128 x BSTR
    uint4*    Bbuf  = (uint4*)(smem + BBUFB);       // 2 x 1024 uint4

    int tid = threadIdx.x, lane = tid & 31, wid = tid >> 5;
    int b = blockIdx.z, split = blockIdx.y;
    int i0 = blockIdx.x * 128;
    int kbase = split * KR;

    // stage s2 chunk (KR floats)
    ((float4*)s2S)[tid] = ((const float4*)(g_s2 + b*NN + kbase))[tid];
    // stage bits: 128 rows x 32 words
    {
        int row = tid >> 1, hh = tid & 1;
        const uint4* src = (const uint4*)(g_adjbits + (size_t)(i0+row)*NW + (kbase >> 5) + hh*16);
        uint4* dst = (uint4*)(bitsS + row*BSTR + hh*16);
#pragma unroll
        for (int q = 0; q < 4; q++) dst[q] = src[q];
    }
    const uint4* srcB = g_WhF4 + (size_t)b * 65536;
    // preload tile 0
    {
        const uint4* s = srcB + (size_t)(kbase >> 4) * 256;
#pragma unroll
        for (int j = 0; j < 4; j++) Bbuf[tid + j*256] = __ldg(s + tid + j*256);
    }
    int r0l = wid*16 + (lane >> 2);
    float s1r0 = g_s1[b*NN + i0 + r0l];
    float s1r1 = g_s1[b*NN + i0 + r0l + 8];
    const unsigned* bw0 = bitsS + r0l * BSTR;
    const unsigned* bw1 = bitsS + (r0l + 8) * BSTR;
    __syncthreads();

    float acc[8][4];
#pragma unroll
    for (int nt = 0; nt < 8; nt++)
#pragma unroll
        for (int c = 0; c < 4; c++) acc[nt][c] = 0.f;
    float z0 = 0.f, z1 = 0.f;

    for (int t = 0; t < NT; t++) {
        int cur = t & 1;
        uint4 st0, st1, st2, st3;
        if (t + 1 < NT) {
            const uint4* s = srcB + (size_t)((kbase >> 4) + (t+1)*4) * 256;
            st0 = __ldg(s + tid);       st1 = __ldg(s + tid + 256);
            st2 = __ldg(s + tid + 512); st3 = __ldg(s + tid + 768);
        }
        const uint4* bb4 = Bbuf + cur*1024;
        unsigned w0  = bw0[2*t], w0b = bw0[2*t + 1];
        unsigned w1  = bw1[2*t], w1b = bw1[2*t + 1];
        uint4 bq[8];
#pragma unroll
        for (int kk = 0; kk < 8; kk++) {
            int kl = t*64 + kk*8 + (lane & 3);
            float s2a = s2S[kl], s2b = s2S[kl + 4];
            unsigned wa = (kk < 4) ? w0 : w0b;
            unsigned wb = (kk < 4) ? w1 : w1b;
            int pos = ((kk & 3) << 3) + (lane & 3);
            float p0 = pexp(s1r0 + s2a, (wa >> pos) & 1u);
            float p1 = pexp(s1r1 + s2a, (wb >> pos) & 1u);
            float p2 = pexp(s1r0 + s2b, (wa >> (pos+4)) & 1u);
            float p3 = pexp(s1r1 + s2b, (wb >> (pos+4)) & 1u);
            z0 += p0 + p2;
            z1 += p1 + p3;
            unsigned a0 = tf32r(p0), a1 = tf32r(p1), a2 = tf32r(p2), a3 = tf32r(p3);
            if ((kk & 1) == 0) {
#pragma unroll
                for (int nt = 0; nt < 8; nt++)
                    bq[nt] = bb4[(kk >> 1)*256 + nt*32 + lane];
            }
#pragma unroll
            for (int nt = 0; nt < 8; nt++) {
                unsigned bx = (kk & 1) ? bq[nt].z : bq[nt].x;
                unsigned by = (kk & 1) ? bq[nt].w : bq[nt].y;
                mma8(acc[nt], a0, a1, a2, a3, bx, by);
            }
        }
        if (t + 1 < NT) {
            uint4* d = Bbuf + (cur^1)*1024;
            d[tid] = st0; d[tid+256] = st1; d[tid+512] = st2; d[tid+768] = st3;
        }
        __syncthreads();
    }

    // Z partials: reduce over the 4 lanes of each quad (deterministic)
    z0 += __shfl_xor_sync(0xffffffffu, z0, 1);
    z0 += __shfl_xor_sync(0xffffffffu, z0, 2);
    z1 += __shfl_xor_sync(0xffffffffu, z1, 1);
    z1 += __shfl_xor_sync(0xffffffffu, z1, 2);
    if ((lane & 3) == 0) {
        g_Zp[split*BB*NN + b*NN + i0 + r0l]     = z0;
        g_Zp[split*BB*NN + b*NN + i0 + r0l + 8] = z1;
    }

    // write split partials
    float* accp = (split == 0 ? g_acc0 : split == 1 ? g_acc1 :
                   split == 2 ? g_acc2 : g_acc3)
                  + ((size_t)(b*NN + i0 + r0l)) * FOUT;
#pragma unroll
    for (int nt = 0; nt < 8; nt++) {
        int col = nt*8 + 2*(lane & 3);
        *(float2*)(accp + col)            = make_float2(acc[nt][0], acc[nt][1]);
        *(float2*)(accp + 8*FOUT + col)   = make_float2(acc[nt][2], acc[nt][3]);
    }
}

// ---------------- K3: combine splits, normalize, ELU -----------------------
__global__ void k_final(float* __restrict__ out) {
    int idx = blockIdx.x * 256 + threadIdx.x;
    float4 v0 = ((const float4*)g_acc0)[idx];
    float4 v1 = ((const float4*)g_acc1)[idx];
    float4 v2 = ((const float4*)g_acc2)[idx];
    float4 v3 = ((const float4*)g_acc3)[idx];
    int row = idx >> 4;
    float Z = g_Zp[row] + g_Zp[BB*NN + row] + g_Zp[2*BB*NN + row] + g_Zp[3*BB*NN + row];
    float inv = 1.f / Z;
    float4 o;
    o.x = elu1((v0.x + v1.x + v2.x + v3.x) * inv);
    o.y = elu1((v0.y + v1.y + v2.y + v3.y) * inv);
    o.z = elu1((v0.z + v1.z + v2.z + v3.z) * inv);
    o.w = elu1((v0.w + v1.w + v2.w + v3.w) * inv);
    ((float4*)out)[idx] = o;
}

// ---------------- launch ---------------------------------------------------
extern "C" void kernel_launch(void* const* d_in, const int* in_sizes, int n_in,
                              void* d_out, int out_size) {
    const float* h   = (const float*)d_in[0];
    const int*   adj = (const int*)  d_in[1];
    const float* W   = (const float*)d_in[2];
    const float* a   = (const float*)d_in[3];
    float* out = (float*)d_out;

    cudaFuncSetAttribute(k_main, cudaFuncAttributeMaxDynamicSharedMemorySize, SMEMB);

    k_proj <<<(BB*NN)/16, 256>>>(h, W, a, adj);
    k_main <<<dim3(NN/128, SPLITS, BB), 256, SMEMB>>>();
    k_final<<<(BB*NN*FOUT)/(4*256), 256>>>(out);
}

// round 10
// speedup vs baseline: 4.7955x; 1.1689x over previous
#include <cuda_runtime.h>
#include <math.h>
#include <stdint.h>

#define NN     4096
#define BB     2
#define FIN    128
#define FOUT   64
#define NW     128
#define ALPHA  0.2f

#define SPLITS  8
#define KR      (NN/SPLITS)     // 512 k per CTA
#define NT      8               // tiles of 64 k

// k_main smem byte offsets
#define BITSB  2048
#define BSTR   20               // 16 words + pad
#define BBUFB  (BITSB + 128*BSTR*4)        // 12288
#define SMEMB  (BBUFB + 2*1024*16)         // 45056

__device__ float    g_s1[BB*NN];
__device__ float    g_s2[BB*NN];
__device__ float    g_Zp[SPLITS*BB*NN];
__device__ unsigned g_adjbits[NN*NW];
__device__ uint4    g_WhF4[BB*65536];     // Wh in B-fragment order, tf32-rounded
__device__ float    g_accA[SPLITS*BB*NN*FOUT];   // 16 MB split partials

__device__ __forceinline__ float elu1(float v) { return v > 0.f ? v : expm1f(v); }
__device__ __forceinline__ unsigned tf32r(float x) {
    unsigned u;
    asm("cvt.rna.tf32.f32 %0, %1;" : "=r"(u) : "f"(x));
    return u;
}
__device__ __forceinline__ void mma8(float* c, unsigned a0, unsigned a1,
                                     unsigned a2, unsigned a3,
                                     unsigned b0, unsigned b1) {
    asm volatile("mma.sync.aligned.m16n8k8.row.col.f32.tf32.tf32.f32 "
        "{%0,%1,%2,%3}, {%4,%5,%6,%7}, {%8,%9}, {%0,%1,%2,%3};"
        : "+f"(c[0]), "+f"(c[1]), "+f"(c[2]), "+f"(c[3])
        : "r"(a0), "r"(a1), "r"(a2), "r"(a3), "r"(b0), "r"(b1));
}
__device__ __forceinline__ float pexp(float e, unsigned bit) {
    float l = fmaxf(e, ALPHA * e);
    float p = __expf(l);
    return bit ? p : 0.f;
}

// ---------------- K1: Wh (fragment layout) + s1 + s2 + adj pack ------------
__global__ __launch_bounds__(256) void k_proj(const float* __restrict__ h,
                                              const float* __restrict__ W,
                                              const float* __restrict__ a,
                                              const int* __restrict__ adj) {
    __shared__ float  Ws[FIN*FOUT];
    __shared__ float  hS[16*FIN];
    __shared__ float2 sred[8][4];
    int tid = threadIdx.x, lane = tid & 31, wid = tid >> 5;
    {
        const float4* w4 = (const float4*)W;
        float4* d4 = (float4*)Ws;
#pragma unroll
        for (int k = 0; k < 8; k++) d4[tid + k*256] = w4[tid + k*256];
    }
    int rowbase = blockIdx.x * 16;
    {
        const float4* h4s = (const float4*)(h + (size_t)rowbase * FIN);
        float4* d4 = (float4*)hS;
        d4[tid] = h4s[tid]; d4[tid+256] = h4s[tid+256];
    }
    __syncthreads();

    // ---- GEMM: each thread -> 4 rows (r4, r4+4, r4+8, r4+12), col o --------
    int o = tid & 63, r4 = tid >> 6;
    float acc0 = 0.f, acc1 = 0.f, acc2 = 0.f, acc3 = 0.f;
    const float4* h4 = (const float4*)hS;
#pragma unroll
    for (int f4 = 0; f4 < 32; f4++) {
        float w0 = Ws[(f4*4+0)*FOUT + o];
        float w1 = Ws[(f4*4+1)*FOUT + o];
        float w2 = Ws[(f4*4+2)*FOUT + o];
        float w3 = Ws[(f4*4+3)*FOUT + o];
        float4 hv0 = h4[(r4+ 0)*32 + f4];
        float4 hv1 = h4[(r4+ 4)*32 + f4];
        float4 hv2 = h4[(r4+ 8)*32 + f4];
        float4 hv3 = h4[(r4+12)*32 + f4];
        acc0 = fmaf(hv0.x,w0, fmaf(hv0.y,w1, fmaf(hv0.z,w2, fmaf(hv0.w,w3, acc0))));
        acc1 = fmaf(hv1.x,w0, fmaf(hv1.y,w1, fmaf(hv1.z,w2, fmaf(hv1.w,w3, acc1))));
        acc2 = fmaf(hv2.x,w0, fmaf(hv2.y,w1, fmaf(hv2.z,w2, fmaf(hv2.w,w3, acc2))));
        acc3 = fmaf(hv3.x,w0, fmaf(hv3.y,w1, fmaf(hv3.z,w2, fmaf(hv3.w,w3, acc3))));
    }
    float a1v = __ldg(a + o), a2v = __ldg(a + FOUT + o);
    unsigned* whf = (unsigned*)g_WhF4;
    float accs[4] = {acc0, acc1, acc2, acc3};
#pragma unroll
    for (int rr = 0; rr < 4; rr++) {
        float acc = accs[rr];
        int gr = rowbase + r4 + rr*4;
        int bb = gr >> 12, k = gr & (NN-1);
        int f4i = ((k >> 4)*8 + (o >> 3))*32 + ((o & 7)*4 + (k & 3));
        whf[(size_t)bb*262144 + (size_t)f4i*4 + ((k >> 2) & 3)] = tf32r(acc);
        float p1 = acc * a1v, p2 = acc * a2v;
#pragma unroll
        for (int off = 16; off; off >>= 1) {
            p1 += __shfl_xor_sync(0xffffffffu, p1, off);
            p2 += __shfl_xor_sync(0xffffffffu, p2, off);
        }
        if (lane == 0) sred[wid][rr] = make_float2(p1, p2);
    }
    __syncthreads();
    if (tid < 16) {
        int rq = tid & 3, rr = tid >> 2;
        float2 x = sred[2*rq][rr], y = sred[2*rq+1][rr];
        g_s1[rowbase + rq + rr*4] = x.x + y.x;
        g_s2[rowbase + rq + rr*4] = x.y + y.y;
    }

    // ---- adj pack: warp-per-row, int4 loads + shuffle bit-merge ------------
    {
        int prow = blockIdx.x * 8 + wid;     // grid 512 * 8 = 4096 rows
        const int4* arow4 = (const int4*)(adj + (size_t)prow * NN);
        int src = (lane & 3) * 8;            // shfl source: group (lane&3)
#pragma unroll
        for (int q = 0; q < 4; q++) {
            int4 v[8];
#pragma unroll
            for (int s = 0; s < 8; s++)
                v[s] = __ldcs(arow4 + q*256 + s*32 + lane);
            unsigned myw = 0;
#pragma unroll
            for (int s = 0; s < 8; s++) {
                // adj values are exactly 0/1
                unsigned nib = ((unsigned)v[s].x & 1u) | (((unsigned)v[s].y & 1u) << 1)
                             | (((unsigned)v[s].z & 1u) << 2) | (((unsigned)v[s].w & 1u) << 3);
                unsigned t;
                t = __shfl_xor_sync(0xffffffffu, nib, 1);
                nib = (lane & 1) ? (t | (nib << 4))  : (nib | (t << 4));
                t = __shfl_xor_sync(0xffffffffu, nib, 2);
                nib = (lane & 2) ? (t | (nib << 8))  : (nib | (t << 8));
                t = __shfl_xor_sync(0xffffffffu, nib, 4);
                nib = (lane & 4) ? (t | (nib << 16)) : (nib | (t << 16));
                unsigned w = __shfl_sync(0xffffffffu, nib, src);
                if ((lane >> 2) == s) myw = w;
            }
            g_adjbits[(size_t)prow * NW + q*32 + lane] = myw;
        }
    }
}

// ---------------- K2: mma.sync tf32 GEMM, K-split 8, fused Z ---------------
// Grid (32 rowtiles, 8 ksplits, 2 batches). 8 warps x 16 exclusive rows.
__global__ __launch_bounds__(256, 2) void k_main() {
    extern __shared__ char smem[];
    float*    s2S   = (float*)smem;                 // KR floats (2 KB)
    unsigned* bitsS = (unsigned*)(smem + BITSB);    // 128 x BSTR
    uint4*    Bbuf  = (uint4*)(smem + BBUFB);       // 2 x 1024 uint4

    int tid = threadIdx.x, lane = tid & 31, wid = tid >> 5;
    int b = blockIdx.z, split = blockIdx.y;
    int i0 = blockIdx.x * 128;
    int kbase = split * KR;

    // stage s2 chunk (KR floats)
    if (tid < KR/4)
        ((float4*)s2S)[tid] = ((const float4*)(g_s2 + b*NN + kbase))[tid];
    // stage bits: 128 rows x 16 words
    {
        int row = tid >> 1, hh = tid & 1;
        const uint4* src = (const uint4*)(g_adjbits + (size_t)(i0+row)*NW + (kbase >> 5) + hh*8);
        uint4* dst = (uint4*)(bitsS + row*BSTR + hh*8);
        dst[0] = src[0]; dst[1] = src[1];
    }
    const uint4* srcB = g_WhF4 + (size_t)b * 65536;
    // preload tile 0
    {
        const uint4* s = srcB + (size_t)(kbase >> 4) * 256;
#pragma unroll
        for (int j = 0; j < 4; j++) Bbuf[tid + j*256] = __ldg(s + tid + j*256);
    }
    int r0l = wid*16 + (lane >> 2);
    float s1r0 = g_s1[b*NN + i0 + r0l];
    float s1r1 = g_s1[b*NN + i0 + r0l + 8];
    const unsigned* bw0 = bitsS + r0l * BSTR;
    const unsigned* bw1 = bitsS + (r0l + 8) * BSTR;
    __syncthreads();

    float acc[8][4];
#pragma unroll
    for (int nt = 0; nt < 8; nt++)
#pragma unroll
        for (int c = 0; c < 4; c++) acc[nt][c] = 0.f;
    float z0 = 0.f, z1 = 0.f;

    for (int t = 0; t < NT; t++) {
        int cur = t & 1;
        uint4 st0, st1, st2, st3;
        if (t + 1 < NT) {
            const uint4* s = srcB + (size_t)((kbase >> 4) + (t+1)*4) * 256;
            st0 = __ldg(s + tid);       st1 = __ldg(s + tid + 256);
            st2 = __ldg(s + tid + 512); st3 = __ldg(s + tid + 768);
        }
        const uint4* bb4 = Bbuf + cur*1024;
        unsigned w0  = bw0[2*t], w0b = bw0[2*t + 1];
        unsigned w1  = bw1[2*t], w1b = bw1[2*t + 1];
        uint4 bq[8];
#pragma unroll
        for (int kk = 0; kk < 8; kk++) {
            int kl = t*64 + kk*8 + (lane & 3);
            float s2a = s2S[kl], s2b = s2S[kl + 4];
            unsigned wa = (kk < 4) ? w0 : w0b;
            unsigned wb = (kk < 4) ? w1 : w1b;
            int pos = ((kk & 3) << 3) + (lane & 3);
            float p0 = pexp(s1r0 + s2a, (wa >> pos) & 1u);
            float p1 = pexp(s1r1 + s2a, (wb >> pos) & 1u);
            float p2 = pexp(s1r0 + s2b, (wa >> (pos+4)) & 1u);
            float p3 = pexp(s1r1 + s2b, (wb >> (pos+4)) & 1u);
            z0 += p0 + p2;
            z1 += p1 + p3;
            unsigned a0 = tf32r(p0), a1 = tf32r(p1), a2 = tf32r(p2), a3 = tf32r(p3);
            if ((kk & 1) == 0) {
#pragma unroll
                for (int nt = 0; nt < 8; nt++)
                    bq[nt] = bb4[(kk >> 1)*256 + nt*32 + lane];
            }
#pragma unroll
            for (int nt = 0; nt < 8; nt++) {
                unsigned bx = (kk & 1) ? bq[nt].z : bq[nt].x;
                unsigned by = (kk & 1) ? bq[nt].w : bq[nt].y;
                mma8(acc[nt], a0, a1, a2, a3, bx, by);
            }
        }
        if (t + 1 < NT) {
            uint4* d = Bbuf + (cur^1)*1024;
            d[tid] = st0; d[tid+256] = st1; d[tid+512] = st2; d[tid+768] = st3;
        }
        __syncthreads();
    }

    // Z partials: reduce over the 4 lanes of each quad (deterministic)
    z0 += __shfl_xor_sync(0xffffffffu, z0, 1);
    z0 += __shfl_xor_sync(0xffffffffu, z0, 2);
    z1 += __shfl_xor_sync(0xffffffffu, z1, 1);
    z1 += __shfl_xor_sync(0xffffffffu, z1, 2);
    if ((lane & 3) == 0) {
        g_Zp[split*BB*NN + b*NN + i0 + r0l]     = z0;
        g_Zp[split*BB*NN + b*NN + i0 + r0l + 8] = z1;
    }

    // write split partials
    float* accp = g_accA + (size_t)split*BB*NN*FOUT
                  + ((size_t)(b*NN + i0 + r0l)) * FOUT;
#pragma unroll
    for (int nt = 0; nt < 8; nt++) {
        int col = nt*8 + 2*(lane & 3);
        *(float2*)(accp + col)            = make_float2(acc[nt][0], acc[nt][1]);
        *(float2*)(accp + 8*FOUT + col)   = make_float2(acc[nt][2], acc[nt][3]);
    }
}

// ---------------- K3: combine splits, normalize, ELU -----------------------
__global__ void k_final(float* __restrict__ out) {
    int idx = blockIdx.x * 256 + threadIdx.x;
    int row = idx >> 4;
    float4 v = make_float4(0.f, 0.f, 0.f, 0.f);
    float Z = 0.f;
#pragma unroll
    for (int s = 0; s < SPLITS; s++) {
        float4 t = ((const float4*)(g_accA + (size_t)s*BB*NN*FOUT))[idx];
        v.x += t.x; v.y += t.y; v.z += t.z; v.w += t.w;
        Z += g_Zp[s*BB*NN + row];
    }
    float inv = 1.f / Z;
    float4 o;
    o.x = elu1(v.x * inv);
    o.y = elu1(v.y * inv);
    o.z = elu1(v.z * inv);
    o.w = elu1(v.w * inv);
    ((float4*)out)[idx] = o;
}

// ---------------- launch ---------------------------------------------------
extern "C" void kernel_launch(void* const* d_in, const int* in_sizes, int n_in,
                              void* d_out, int out_size) {
    const float* h   = (const float*)d_in[0];
    const int*   adj = (const int*)  d_in[1];
    const float* W   = (const float*)d_in[2];
    const float* a   = (const float*)d_in[3];
    float* out = (float*)d_out;

    cudaFuncSetAttribute(k_main, cudaFuncAttributeMaxDynamicSharedMemorySize, SMEMB);

    k_proj <<<(BB*NN)/16, 256>>>(h, W, a, adj);
    k_main <<<dim3(NN/128, SPLITS, BB), 256, SMEMB>>>();
    k_final<<<(BB*NN*FOUT)/(4*256), 256>>>(out);
}